// round 4
// baseline (speedup 1.0000x reference)
#include <cuda_runtime.h>

#define HW   9216            // 96*96
#define NPIX 589824          // 64*HW

#define INV_LOG49 0.2569487252483261f
#define INV_LOG81 0.2275598569527368f
#define L2E       1.4426950408889634f

__device__ __forceinline__ float ex2(float x) {
    float y;
    asm("ex2.approx.ftz.f32 %0, %1;" : "=f"(y) : "f"(x));
    return y;
}

template<int START, int CNT>
__device__ __forceinline__ void load_argmax2(const float* __restrict__ px,
                                             float2* val, float2& pm, int2& pi) {
#pragma unroll
    for (int k = 0; k < CNT; k++)
        val[k] = *reinterpret_cast<const float2*>(px + (size_t)(START + k) * HW);
    pm.x = val[0].x; pm.y = val[0].y;
    pi.x = START;    pi.y = START;
#pragma unroll
    for (int k = 1; k < CNT; k++) {
        if (val[k].x > pm.x) { pm.x = val[k].x; pi.x = START + k; }
        if (val[k].y > pm.y) { pm.y = val[k].y; pi.y = START + k; }
    }
}

// acc layout: [0..5] pixel A (Sg,Tg,Sl,Tl,Sfx,Sfy), [6..11] pixel B
template<int START, int CNT>
__device__ __forceinline__ void moments2(const float2* val,
                                         float aA, float aB,   // -M*log2e per pixel
                                         unsigned rbA, unsigned cbA,
                                         unsigned rbB, unsigned cbB,
                                         float* acc) {
#pragma unroll
    for (int k = 0; k < CNT; k++) {
        const int i = START + k;
        const int u = i / 9;
        const int v = i - u * 9;
        const bool ruA = (rbA >> u) & 1u;       // row test: hoistable/CSE per u
        const bool ruB = (rbB >> u) & 1u;

        float vx = val[k].x, vy = val[k].y;
        float eA = ex2(fmaf(vx, L2E, aA));
        float eB = ex2(fmaf(vy, L2E, aB));
        acc[0] += eA;
        acc[1]  = fmaf(vx, eA, acc[1]);
        acc[6] += eB;
        acc[7]  = fmaf(vy, eB, acc[7]);
        if (ruA && ((cbA >> v) & 1u)) {
            acc[2] += eA;
            acc[3]  = fmaf(vx, eA, acc[3]);
            acc[4]  = fmaf(eA, (float)(u - 4), acc[4]);
            acc[5]  = fmaf(eA, (float)(v - 4), acc[5]);
        }
        if (ruB && ((cbB >> v) & 1u)) {
            acc[8]  += eB;
            acc[9]   = fmaf(vy, eB, acc[9]);
            acc[10]  = fmaf(eB, (float)(u - 4), acc[10]);
            acc[11]  = fmaf(eB, (float)(v - 4), acc[11]);
        }
    }
}

__global__ __launch_bounds__(128)
void vcn_kernel(const float* __restrict__ x, float* __restrict__ out) {
    const int lane = threadIdx.x;
    const int yy   = threadIdx.y;

    const int pix0 = (blockIdx.x * 32 + lane) * 2;   // even; pair {pix0, pix0+1}
    const int b  = pix0 / HW;
    const int hw = pix0 - b * HW;
    const float* px = x + (size_t)b * 81 * HW + hw;

    __shared__ float2 smax[4][32];
    __shared__ int2   sidx[4][32];
    __shared__ float  spart[12][4][32];

    float2 val[21];
    float2 pm;
    int2   pi;

    switch (yy) {
        case 0:  load_argmax2< 0, 21>(px, val, pm, pi); break;
        case 1:  load_argmax2<21, 20>(px, val, pm, pi); break;
        case 2:  load_argmax2<41, 20>(px, val, pm, pi); break;
        default: load_argmax2<61, 20>(px, val, pm, pi); break;
    }
    smax[yy][lane] = pm;
    sidx[yy][lane] = pi;
    __syncthreads();

    float MA = smax[0][lane].x, MB = smax[0][lane].y;
    int   iA = sidx[0][lane].x, iB = sidx[0][lane].y;
#pragma unroll
    for (int q = 1; q < 4; q++) {
        float2 m2 = smax[q][lane];
        int2   j2 = sidx[q][lane];
        if (m2.x > MA) { MA = m2.x; iA = j2.x; }   // ascending q, strict '>'
        if (m2.y > MB) { MB = m2.y; iB = j2.y; }
    }

    const int iuA = iA / 9, ivA = iA - iuA * 9;
    const int iuB = iB / 9, ivB = iB - iuB * 9;
    const unsigned rbA = (0x7Fu << iuA) >> 3, cbA = (0x7Fu << ivA) >> 3;
    const unsigned rbB = (0x7Fu << iuB) >> 3, cbB = (0x7Fu << ivB) >> 3;

    float acc[12];
#pragma unroll
    for (int j = 0; j < 12; j++) acc[j] = 0.f;
    const float aA = -MA * L2E, aB = -MB * L2E;

    switch (yy) {
        case 0:  moments2< 0, 21>(val, aA, aB, rbA, cbA, rbB, cbB, acc); break;
        case 1:  moments2<21, 20>(val, aA, aB, rbA, cbA, rbB, cbB, acc); break;
        case 2:  moments2<41, 20>(val, aA, aB, rbA, cbA, rbB, cbB, acc); break;
        default: moments2<61, 20>(val, aA, aB, rbA, cbA, rbB, cbB, acc); break;
    }
#pragma unroll
    for (int j = 0; j < 12; j++) spart[j][yy][lane] = acc[j];
    __syncthreads();

    if (yy == 0) {
#pragma unroll
        for (int q = 1; q < 4; q++)
#pragma unroll
            for (int j = 0; j < 12; j++) acc[j] += spart[j][q][lane];

        float2 flow_x, flow_y, ent_l, ent_g;

        {   // pixel A
            float invSl = 1.0f / acc[2], invSg = 1.0f / acc[0];
            flow_x.x = acc[4] * invSl;
            flow_y.x = acc[5] * invSl;
            ent_l.x  = (__logf(acc[2]) - acc[3] * invSl + MA) * INV_LOG49;
            ent_g.x  = (__logf(acc[0]) - acc[1] * invSg + MA) * INV_LOG81;
        }
        {   // pixel B
            float invSl = 1.0f / acc[8], invSg = 1.0f / acc[6];
            flow_x.y = acc[10] * invSl;
            flow_y.y = acc[11] * invSl;
            ent_l.y  = (__logf(acc[8]) - acc[9] * invSl + MB) * INV_LOG49;
            ent_g.y  = (__logf(acc[6]) - acc[7] * invSg + MB) * INV_LOG81;
        }

        float* o = out + (size_t)b * 4 * HW + hw;
        *reinterpret_cast<float2*>(o)          = flow_x;
        *reinterpret_cast<float2*>(o + HW)     = flow_y;
        *reinterpret_cast<float2*>(o + 2 * HW) = ent_l;
        *reinterpret_cast<float2*>(o + 3 * HW) = ent_g;
    }
}

extern "C" void kernel_launch(void* const* d_in, const int* in_sizes, int n_in,
                              void* d_out, int out_size) {
    const float* x = (const float*)d_in[0];
    float* out = (float*)d_out;
    dim3 block(32, 4);
    vcn_kernel<<<NPIX / 64, block>>>(x, out);   // 9216 blocks, 64 pixels each
}

// round 5
// speedup vs baseline: 1.0102x; 1.0102x over previous
#include <cuda_runtime.h>

#define HW   9216            // 96*96
#define NPIX 589824          // 64*HW

#define INV_LOG49 0.2569487252483261f
#define INV_LOG81 0.2275598569527368f
#define L2E       1.4426950408889634f

__device__ __forceinline__ float ex2(float x) {
    float y;
    asm("ex2.approx.ftz.f32 %0, %1;" : "=f"(y) : "f"(x));
    return y;
}

// Pass 1: stream planes [START, START+CNT), track max + first-occurrence index.
template<int START, int CNT>
__device__ __forceinline__ void argmax_pass(const float* __restrict__ px,
                                            float& pm, int& pi) {
    float t[7];
    pm = __int_as_float(0xff800000);   // -inf
    pi = START;
#pragma unroll
    for (int k0 = 0; k0 < CNT; k0 += 7) {
        const int n = (CNT - k0 < 7) ? (CNT - k0) : 7;
#pragma unroll
        for (int j = 0; j < n; j++)
            t[j] = px[(size_t)(START + k0 + j) * HW];
#pragma unroll
        for (int j = 0; j < n; j++)
            if (t[j] > pm) { pm = t[j]; pi = START + k0 + j; }
    }
}

// Pass 2: reload (L1/L2-resident) and accumulate the 6 moments.
template<int START, int CNT>
__device__ __forceinline__ void moments_pass(const float* __restrict__ px,
                                             float nML2E,
                                             unsigned rowbits, unsigned colbits,
                                             float* acc) {
    float t[7];
#pragma unroll
    for (int k0 = 0; k0 < CNT; k0 += 7) {
        const int n = (CNT - k0 < 7) ? (CNT - k0) : 7;
#pragma unroll
        for (int j = 0; j < n; j++)
            t[j] = px[(size_t)(START + k0 + j) * HW];
#pragma unroll
        for (int j = 0; j < n; j++) {
            const int i = START + k0 + j;      // compile-time
            const int u = i / 9;
            const int v = i - u * 9;
            float e = ex2(fmaf(t[j], L2E, nML2E));   // exp(val - M)
            acc[0] += e;                              // Sg
            acc[1]  = fmaf(t[j], e, acc[1]);          // T'g = sum val*e
            if ((rowbits >> u) & (colbits >> v) & 1u) {
                acc[2] += e;                          // Sl
                acc[3]  = fmaf(t[j], e, acc[3]);      // T'l
                acc[4]  = fmaf(e, (float)(u - 4), acc[4]); // Sfx
                acc[5]  = fmaf(e, (float)(v - 4), acc[5]); // Sfy
            }
        }
    }
}

__global__ __launch_bounds__(128, 16)
void vcn_kernel(const float* __restrict__ x, float* __restrict__ out) {
    const int lane = threadIdx.x;
    const int yy   = threadIdx.y;

    const int pixel = blockIdx.x * 32 + lane;
    const int b  = pixel / HW;
    const int hw = pixel - b * HW;
    const float* px = x + (size_t)b * 81 * HW + hw;

    __shared__ float smax[4][32];
    __shared__ int   sidx[4][32];
    __shared__ float spart[6][4][32];

    float pm;
    int   pi;
    switch (yy) {
        case 0:  argmax_pass< 0, 21>(px, pm, pi); break;
        case 1:  argmax_pass<21, 20>(px, pm, pi); break;
        case 2:  argmax_pass<41, 20>(px, pm, pi); break;
        default: argmax_pass<61, 20>(px, pm, pi); break;
    }
    smax[yy][lane] = pm;
    sidx[yy][lane] = pi;
    __syncthreads();

    // Combine argmax (ascending yy + strict '>' keeps first occurrence).
    float M    = smax[0][lane];
    int   amax = sidx[0][lane];
#pragma unroll
    for (int q = 1; q < 4; q++) {
        float m2 = smax[q][lane];
        if (m2 > M) { M = m2; amax = sidx[q][lane]; }
    }

    const int iu = amax / 9;
    const int iv = amax - iu * 9;
    const unsigned rowbits = (0x7Fu << iu) >> 3;   // bit u set iff |u-iu|<=3
    const unsigned colbits = (0x7Fu << iv) >> 3;

    float acc[6] = {0.f, 0.f, 0.f, 0.f, 0.f, 0.f};
    const float nML2E = -M * L2E;
    switch (yy) {
        case 0:  moments_pass< 0, 21>(px, nML2E, rowbits, colbits, acc); break;
        case 1:  moments_pass<21, 20>(px, nML2E, rowbits, colbits, acc); break;
        case 2:  moments_pass<41, 20>(px, nML2E, rowbits, colbits, acc); break;
        default: moments_pass<61, 20>(px, nML2E, rowbits, colbits, acc); break;
    }
#pragma unroll
    for (int j = 0; j < 6; j++) spart[j][yy][lane] = acc[j];
    __syncthreads();

    // Final combine + output (warp-row 0; coalesced stores).
    if (yy == 0) {
#pragma unroll
        for (int q = 1; q < 4; q++)
#pragma unroll
            for (int j = 0; j < 6; j++) acc[j] += spart[j][q][lane];

        float Sg = acc[0], Tg = acc[1], Sl = acc[2], Tl = acc[3];
        float invSl = 1.0f / Sl;
        float invSg = 1.0f / Sg;
        // -sum p log p = log S - sum(val*e)/S + M
        float entl = (__logf(Sl) - Tl * invSl + M) * INV_LOG49;
        float entg = (__logf(Sg) - Tg * invSg + M) * INV_LOG81;

        float* o = out + (size_t)b * 4 * HW + hw;
        o[0]      = acc[4] * invSl;
        o[HW]     = acc[5] * invSl;
        o[2 * HW] = entl;
        o[3 * HW] = entg;
    }
}

extern "C" void kernel_launch(void* const* d_in, const int* in_sizes, int n_in,
                              void* d_out, int out_size) {
    const float* x = (const float*)d_in[0];
    float* out = (float*)d_out;
    dim3 block(32, 4);
    vcn_kernel<<<NPIX / 32, block>>>(x, out);   // 18432 blocks
}